// round 9
// baseline (speedup 1.0000x reference)
#include <cuda_runtime.h>
#include <cuda_bf16.h>
#include <cstdint>
#include <math.h>

#define BATCH 8
#define CHN 512
#define NPIX 4096
#define GROUPS 32
#define CPG 16

// ---------------- scratch (__device__ globals) -------------------------------
__device__ __nv_bfloat16 g_ht[(size_t)BATCH*NPIX*CHN];      // h^T  [b][i][c] bf16
__device__ uint8_t       g_qt8[(size_t)BATCH*NPIX*CHN];     // q^T  [b][i][c] e4m3
__device__ uint8_t       g_kt8[(size_t)BATCH*NPIX*CHN];     // k^T  [b][j][c] e4m3
__device__ uint8_t       g_v8 [(size_t)BATCH*CHN*NPIX];     // v    [b][c][j] e4m3
__device__ __nv_bfloat16 g_ot[(size_t)BATCH*NPIX*CHN];      // o^T  [b][i][c] bf16
__device__ __nv_bfloat16 g_attn[(size_t)BATCH*NPIX*NPIX];   // logits [b][i][j] bf16
__device__ uint8_t       g_attn8[(size_t)BATCH*NPIX*NPIX];  // softmax(attn)*256 e4m3
__device__ __nv_bfloat16 g_wq[CHN*CHN];
__device__ __nv_bfloat16 g_wk[CHN*CHN];
__device__ __nv_bfloat16 g_wv[CHN*CHN];
__device__ __nv_bfloat16 g_wp[CHN*CHN];

// ---------------- helpers ------------------------------------------------------
__device__ __forceinline__ uint32_t smem_u32(const void* p) {
    uint32_t a;
    asm("{ .reg .u64 t; cvta.to.shared.u64 t, %1; cvt.u32.u64 %0, t; }" : "=r"(a) : "l"(p));
    return a;
}
__device__ __forceinline__ void cpa16(uint32_t s, const void* g) {
    asm volatile("cp.async.cg.shared.global [%0], [%1], 16;" :: "r"(s), "l"(g) : "memory");
}
#define CPA_COMMIT() asm volatile("cp.async.commit_group;" ::: "memory")
#define CPA_WAIT2()  asm volatile("cp.async.wait_group 2;" ::: "memory")
#define CPA_WAIT0()  asm volatile("cp.async.wait_group 0;" ::: "memory")

__device__ __forceinline__ void ldsm4(uint32_t addr, uint32_t& r0, uint32_t& r1,
                                      uint32_t& r2, uint32_t& r3) {
    asm volatile("ldmatrix.sync.aligned.m8n8.x4.shared.b16 {%0,%1,%2,%3}, [%4];"
                 : "=r"(r0), "=r"(r1), "=r"(r2), "=r"(r3) : "r"(addr));
}
// pack two fp32 -> e4m3x2 (byte0 = lo, byte1 = hi)
__device__ __forceinline__ uint16_t pack_e4m3(float lo, float hi) {
    uint16_t r;
    asm("cvt.rn.satfinite.e4m3x2.f32 %0, %1, %2;" : "=h"(r) : "f"(hi), "f"(lo));
    return r;
}

// ---------------- shared tile geometry (both GEMMs: 128x128 tiles, 32KB/stage) --
#define BM 128
#define BN 128
#define NSTAGE 3
#define ABYTES (BM*128)
#define BBYTES (BN*128)
#define STAGE_BYTES (ABYTES + BBYTES)
#define SMEM_TOTAL (NSTAGE*STAGE_BYTES)   // 96 KB

// ---------------- bf16 mma.sync GEMM (convs + proj) ---------------------------
// C[m][n] = scale*(sum_k A[m][k]*B[n][k]) + bias_m[m] + bias_n[n]
// mode: 0 = bf16 out, 1 = fp32 out + residual, 2 = e4m3 out
#define BK 64

__global__ void __launch_bounds__(128, 2)
gemm_tc(const __nv_bfloat16* __restrict__ A, size_t strideA,
        const __nv_bfloat16* __restrict__ B, size_t strideB,
        void* __restrict__ Cv, size_t strideC, int ldC,
        const float* __restrict__ bias_m,
        const float* __restrict__ bias_n,
        const float* __restrict__ resid,
        float scale, int K, int mode) {
    extern __shared__ char smem[];
    uint32_t sb = smem_u32(smem);

    int tid  = threadIdx.x;
    int wid  = tid >> 5, lane = tid & 31;
    int wm = wid >> 1;
    int wn = wid & 1;
    int m0 = blockIdx.y * BM;
    int n0 = blockIdx.x * BN;
    const __nv_bfloat16* Ab = A + (size_t)blockIdx.z*strideA + (size_t)m0*K;
    const __nv_bfloat16* Bb = B + (size_t)blockIdx.z*strideB + (size_t)n0*K;

    float acc[4][8][4];
    #pragma unroll
    for (int i = 0; i < 4; i++)
        #pragma unroll
        for (int j = 0; j < 8; j++)
            #pragma unroll
            for (int r = 0; r < 4; r++) acc[i][j][r] = 0.f;

    auto copy_stage = [&](int s, int k0) {
        uint32_t ab  = sb + s*STAGE_BYTES;
        uint32_t bbs = ab + ABYTES;
        #pragma unroll
        for (int i = 0; i < 8; i++) {
            int q = i*128 + tid;
            int r = q >> 3, c = q & 7;
            uint32_t off = r*128 + ((c ^ (r & 7)) << 4);
            cpa16(ab  + off, Ab + (size_t)r*K + k0 + c*8);
            cpa16(bbs + off, Bb + (size_t)r*K + k0 + c*8);
        }
        CPA_COMMIT();
    };

    int nt = K / BK;
    copy_stage(0, 0);
    copy_stage(1, BK);

    int arow = wm*64 + (lane & 15);
    int akc  = lane >> 4;
    int brow = wn*64 + (lane & 7) + ((lane >> 4) << 3);
    int bkc  = (lane >> 3) & 1;
    int xra = arow & 7, xrb = brow & 7;

    uint32_t a_base[4], b_base[4], xa[4], xb[4];
    #pragma unroll
    for (int i = 0; i < 4; i++) {
        a_base[i] = (uint32_t)(arow + i*16) * 128;
        b_base[i] = (uint32_t)(brow + i*16) * 128;
        xa[i] = (uint32_t)(((i*2 + akc) ^ xra) << 4);
        xb[i] = (uint32_t)(((i*2 + bkc) ^ xrb) << 4);
    }

    for (int it = 0; it < nt; it++) {
        if (it + 2 < nt) copy_stage((it + 2) % NSTAGE, (it + 2)*BK);
        if (it + 2 < nt) { CPA_WAIT2(); } else { CPA_WAIT0(); }
        __syncthreads();

        uint32_t as = sb + (it % NSTAGE)*STAGE_BYTES;
        uint32_t bs = as + ABYTES;

        #pragma unroll
        for (int ks = 0; ks < 4; ks++) {
            uint32_t af[4][4], bf[8][2];
            #pragma unroll
            for (int am = 0; am < 4; am++)
                ldsm4(as + a_base[am] + xa[ks], af[am][0], af[am][1], af[am][2], af[am][3]);
            #pragma unroll
            for (int bt = 0; bt < 4; bt++)
                ldsm4(bs + b_base[bt] + xb[ks], bf[bt*2][0], bf[bt*2][1],
                                                bf[bt*2+1][0], bf[bt*2+1][1]);
            #pragma unroll
            for (int am = 0; am < 4; am++)
                #pragma unroll
                for (int an = 0; an < 8; an++) {
                    float* c = acc[am][an];
                    asm volatile(
                        "mma.sync.aligned.m16n8k16.row.col.f32.bf16.bf16.f32 "
                        "{%0,%1,%2,%3}, {%4,%5,%6,%7}, {%8,%9}, {%0,%1,%2,%3};"
                        : "+f"(c[0]), "+f"(c[1]), "+f"(c[2]), "+f"(c[3])
                        : "r"(af[am][0]), "r"(af[am][1]), "r"(af[am][2]), "r"(af[am][3]),
                          "r"(bf[an][0]), "r"(bf[an][1]));
                }
        }
        __syncthreads();
    }

    int g = lane >> 2, t = lane & 3;
    #pragma unroll
    for (int am = 0; am < 4; am++) {
        int ml = m0 + wm*64 + am*16 + g;
        int mh = ml + 8;
        float bml = bias_m ? bias_m[ml] : 0.f;
        float bmh = bias_m ? bias_m[mh] : 0.f;
        size_t rl = (size_t)blockIdx.z*strideC + (size_t)ml*ldC;
        size_t rh = (size_t)blockIdx.z*strideC + (size_t)mh*ldC;
        #pragma unroll
        for (int an = 0; an < 8; an++) {
            int ne = n0 + wn*64 + an*8 + 2*t;
            float v0 = acc[am][an][0]*scale + bml;
            float v1 = acc[am][an][1]*scale + bml;
            float v2 = acc[am][an][2]*scale + bmh;
            float v3 = acc[am][an][3]*scale + bmh;
            if (bias_n) {
                float b0 = __ldg(bias_n + ne), b1 = __ldg(bias_n + ne + 1);
                v0 += b0; v1 += b1; v2 += b0; v3 += b1;
            }
            if (mode == 0) {
                __nv_bfloat16* C = (__nv_bfloat16*)Cv;
                *reinterpret_cast<__nv_bfloat162*>(C + rl + ne) =
                    __nv_bfloat162{__float2bfloat16(v0), __float2bfloat16(v1)};
                *reinterpret_cast<__nv_bfloat162*>(C + rh + ne) =
                    __nv_bfloat162{__float2bfloat16(v2), __float2bfloat16(v3)};
            } else if (mode == 1) {
                float* C = (float*)Cv;
                float2 r0 = *reinterpret_cast<const float2*>(resid + rl + ne);
                float2 r1 = *reinterpret_cast<const float2*>(resid + rh + ne);
                *reinterpret_cast<float2*>(C + rl + ne) = float2{v0 + r0.x, v1 + r0.y};
                *reinterpret_cast<float2*>(C + rh + ne) = float2{v2 + r1.x, v3 + r1.y};
            } else {
                uint8_t* C = (uint8_t*)Cv;
                *reinterpret_cast<uint16_t*>(C + rl + ne) = pack_e4m3(v0, v1);
                *reinterpret_cast<uint16_t*>(C + rh + ne) = pack_e4m3(v2, v3);
            }
        }
    }
}

// ---------------- e4m3 mma.sync GEMM (logits + attn@V) ------------------------
// C[m][n] (bf16) = scale * sum_k A[m][k]*B[n][k]; A,B e4m3 k-contiguous
#define BKF8 128   // 128 fp8 elements = 128 B per row-tile

__global__ void __launch_bounds__(128, 2)
gemm_f8(const uint8_t* __restrict__ A, size_t strideA,
        const uint8_t* __restrict__ B, size_t strideB,
        __nv_bfloat16* __restrict__ C, size_t strideC, int ldC,
        float scale, int K) {
    extern __shared__ char smem[];
    uint32_t sb = smem_u32(smem);

    int tid  = threadIdx.x;
    int wid  = tid >> 5, lane = tid & 31;
    int wm = wid >> 1;
    int wn = wid & 1;
    int m0 = blockIdx.y * BM;
    int n0 = blockIdx.x * BN;
    const uint8_t* Ab = A + (size_t)blockIdx.z*strideA + (size_t)m0*K;
    const uint8_t* Bb = B + (size_t)blockIdx.z*strideB + (size_t)n0*K;

    float acc[4][8][4];
    #pragma unroll
    for (int i = 0; i < 4; i++)
        #pragma unroll
        for (int j = 0; j < 8; j++)
            #pragma unroll
            for (int r = 0; r < 4; r++) acc[i][j][r] = 0.f;

    auto copy_stage = [&](int s, int k0) {
        uint32_t ab  = sb + s*STAGE_BYTES;
        uint32_t bbs = ab + ABYTES;
        #pragma unroll
        for (int i = 0; i < 8; i++) {
            int q = i*128 + tid;
            int r = q >> 3, c = q & 7;
            uint32_t off = r*128 + ((c ^ (r & 7)) << 4);
            cpa16(ab  + off, Ab + (size_t)r*K + k0 + c*16);
            cpa16(bbs + off, Bb + (size_t)r*K + k0 + c*16);
        }
        CPA_COMMIT();
    };

    int nt = K / BKF8;
    copy_stage(0, 0);
    copy_stage(1, BKF8);

    int arow = wm*64 + (lane & 15);
    int akc  = lane >> 4;
    int brow = wn*64 + (lane & 7) + ((lane >> 4) << 3);
    int bkc  = (lane >> 3) & 1;
    int xra = arow & 7, xrb = brow & 7;

    uint32_t a_base[4], b_base[4], xa[4], xb[4];
    #pragma unroll
    for (int i = 0; i < 4; i++) {
        a_base[i] = (uint32_t)(arow + i*16) * 128;
        b_base[i] = (uint32_t)(brow + i*16) * 128;
        xa[i] = (uint32_t)(((i*2 + akc) ^ xra) << 4);
        xb[i] = (uint32_t)(((i*2 + bkc) ^ xrb) << 4);
    }

    for (int it = 0; it < nt; it++) {
        if (it + 2 < nt) copy_stage((it + 2) % NSTAGE, (it + 2)*BKF8);
        if (it + 2 < nt) { CPA_WAIT2(); } else { CPA_WAIT0(); }
        __syncthreads();

        uint32_t as = sb + (it % NSTAGE)*STAGE_BYTES;
        uint32_t bs = as + ABYTES;

        #pragma unroll
        for (int ks = 0; ks < 4; ks++) {     // 4 x k32 (32B each)
            uint32_t af[4][4], bf[8][2];
            #pragma unroll
            for (int am = 0; am < 4; am++)
                ldsm4(as + a_base[am] + xa[ks], af[am][0], af[am][1], af[am][2], af[am][3]);
            #pragma unroll
            for (int bt = 0; bt < 4; bt++)
                ldsm4(bs + b_base[bt] + xb[ks], bf[bt*2][0], bf[bt*2][1],
                                                bf[bt*2+1][0], bf[bt*2+1][1]);
            #pragma unroll
            for (int am = 0; am < 4; am++)
                #pragma unroll
                for (int an = 0; an < 8; an++) {
                    float* c = acc[am][an];
                    asm volatile(
                        "mma.sync.aligned.m16n8k32.row.col.f32.e4m3.e4m3.f32 "
                        "{%0,%1,%2,%3}, {%4,%5,%6,%7}, {%8,%9}, {%0,%1,%2,%3};"
                        : "+f"(c[0]), "+f"(c[1]), "+f"(c[2]), "+f"(c[3])
                        : "r"(af[am][0]), "r"(af[am][1]), "r"(af[am][2]), "r"(af[am][3]),
                          "r"(bf[an][0]), "r"(bf[an][1]));
                }
        }
        __syncthreads();
    }

    int g = lane >> 2, t = lane & 3;
    #pragma unroll
    for (int am = 0; am < 4; am++) {
        int ml = m0 + wm*64 + am*16 + g;
        int mh = ml + 8;
        size_t rl = (size_t)blockIdx.z*strideC + (size_t)ml*ldC;
        size_t rh = (size_t)blockIdx.z*strideC + (size_t)mh*ldC;
        #pragma unroll
        for (int an = 0; an < 8; an++) {
            int ne = n0 + wn*64 + an*8 + 2*t;
            *reinterpret_cast<__nv_bfloat162*>(C + rl + ne) =
                __nv_bfloat162{__float2bfloat16(acc[am][an][0]*scale),
                               __float2bfloat16(acc[am][an][1]*scale)};
            *reinterpret_cast<__nv_bfloat162*>(C + rh + ne) =
                __nv_bfloat162{__float2bfloat16(acc[am][an][2]*scale),
                               __float2bfloat16(acc[am][an][3]*scale)};
        }
    }
}

// ---------------- fp32 -> bf16 weight convert (all 4 weights, 1 launch) -------
#define WN (CHN*CHN)
__global__ void cvt4_kernel(const float* __restrict__ s0, const float* __restrict__ s1,
                            const float* __restrict__ s2, const float* __restrict__ s3,
                            __nv_bfloat16* __restrict__ d0, __nv_bfloat16* __restrict__ d1,
                            __nv_bfloat16* __restrict__ d2, __nv_bfloat16* __restrict__ d3) {
    int i = blockIdx.x * blockDim.x + threadIdx.x;
    int sel = i >> 18;
    int off = i & (WN - 1);
    const float* s = sel == 0 ? s0 : sel == 1 ? s1 : sel == 2 ? s2 : s3;
    __nv_bfloat16* d = sel == 0 ? d0 : sel == 1 ? d1 : sel == 2 ? d2 : d3;
    d[off] = __float2bfloat16(s[off]);
}

// ---------------- GroupNorm -> h^T bf16 [b][i][c] -----------------------------
__global__ void gn_kernel(const float* __restrict__ x,
                          const float* __restrict__ w,
                          const float* __restrict__ b,
                          __nv_bfloat16* __restrict__ ht) {
    int batch = blockIdx.x >> 5;
    int grp   = blockIdx.x & 31;
    const float* xp = x + ((size_t)batch*CHN + (size_t)grp*CPG) * NPIX;
    const int GE = CPG * NPIX;
    int tid = threadIdx.x;

    float s = 0.f, ss = 0.f;
    for (int i = tid; i < GE; i += 256) {
        float v = xp[i];
        s += v; ss += v*v;
    }
    __shared__ float r1[256], r2[256];
    r1[tid] = s; r2[tid] = ss;
    __syncthreads();
    for (int st = 128; st > 0; st >>= 1) {
        if (tid < st) { r1[tid] += r1[tid+st]; r2[tid] += r2[tid+st]; }
        __syncthreads();
    }
    float mean = r1[0] / (float)GE;
    float var  = r2[0] / (float)GE - mean*mean;
    float rstd = rsqrtf(var + 1e-6f);

    float wl[CPG], bl[CPG];
    #pragma unroll
    for (int c = 0; c < CPG; c++) { wl[c] = w[grp*CPG+c]; bl[c] = b[grp*CPG+c]; }

    for (int n = tid; n < NPIX; n += 256) {
        union { __nv_bfloat16 v[CPG]; uint4 u[2]; } pk;
        #pragma unroll
        for (int c = 0; c < CPG; c++) {
            float xv = xp[(size_t)c*NPIX + n];
            pk.v[c] = __float2bfloat16((xv - mean) * rstd * wl[c] + bl[c]);
        }
        uint4* dst = reinterpret_cast<uint4*>(ht + ((size_t)batch*NPIX + n)*CHN + grp*CPG);
        dst[0] = pk.u[0]; dst[1] = pk.u[1];
    }
}

// ---------------- row softmax: bf16 in -> e4m3 (*256) out ----------------------
__global__ void softmax_kernel(const __nv_bfloat16* __restrict__ attn,
                               uint8_t* __restrict__ attn8) {
    const __nv_bfloat16* p = attn + (size_t)blockIdx.x * NPIX;
    uint8_t* p8 = attn8 + (size_t)blockIdx.x * NPIX;
    __shared__ float buf[NPIX];
    __shared__ float red[8];
    int tid = threadIdx.x, lane = tid & 31, wid = tid >> 5;

    float mx = -1e30f;
    for (int i = tid; i < NPIX/8; i += 256) {
        uint4 raw = reinterpret_cast<const uint4*>(p)[i];
        const __nv_bfloat162* h2 = reinterpret_cast<const __nv_bfloat162*>(&raw);
        #pragma unroll
        for (int j = 0; j < 4; j++) {
            float2 f = __bfloat1622float2(h2[j]);
            buf[i*8 + 2*j]   = f.x;
            buf[i*8 + 2*j+1] = f.y;
            mx = fmaxf(mx, fmaxf(f.x, f.y));
        }
    }
    #pragma unroll
    for (int o = 16; o > 0; o >>= 1) mx = fmaxf(mx, __shfl_xor_sync(0xffffffffu, mx, o));
    if (lane == 0) red[wid] = mx;
    __syncthreads();
    if (tid == 0) {
        float m = red[0];
        #pragma unroll
        for (int i = 1; i < 8; i++) m = fmaxf(m, red[i]);
        red[0] = m;
    }
    __syncthreads();
    mx = red[0];
    __syncthreads();

    float s = 0.f;
    for (int i = tid; i < NPIX; i += 256) {
        float e = __expf(buf[i] - mx);
        buf[i] = e;
        s += e;
    }
    #pragma unroll
    for (int o = 16; o > 0; o >>= 1) s += __shfl_xor_sync(0xffffffffu, s, o);
    if (lane == 0) red[wid] = s;
    __syncthreads();
    if (tid == 0) {
        float m = 0.f;
        #pragma unroll
        for (int i = 0; i < 8; i++) m += red[i];
        red[0] = m;
    }
    __syncthreads();
    float inv = 256.0f / red[0];    // store attn * 256 in e4m3

    for (int i = tid; i < NPIX/16; i += 256) {
        union { uint16_t h[8]; uint4 u; } pk;
        #pragma unroll
        for (int j = 0; j < 8; j++)
            pk.h[j] = pack_e4m3(buf[i*16 + 2*j] * inv, buf[i*16 + 2*j + 1] * inv);
        reinterpret_cast<uint4*>(p8)[i] = pk.u;
    }
}

// ---------------- launch -------------------------------------------------------
extern "C" void kernel_launch(void* const* d_in, const int* in_sizes, int n_in,
                              void* d_out, int out_size) {
    const float* x    = (const float*)d_in[0];
    const float* gn_w = (const float*)d_in[1];
    const float* gn_b = (const float*)d_in[2];
    const float* q_w  = (const float*)d_in[3];
    const float* q_b  = (const float*)d_in[4];
    const float* k_w  = (const float*)d_in[5];
    const float* k_b  = (const float*)d_in[6];
    const float* v_w  = (const float*)d_in[7];
    const float* v_b  = (const float*)d_in[8];
    const float* p_w  = (const float*)d_in[9];
    const float* p_b  = (const float*)d_in[10];
    float* out = (float*)d_out;

    __nv_bfloat16 *ht, *ot, *attn, *wq, *wk, *wv, *wp;
    uint8_t *qt8, *kt8, *v8, *attn8;
    cudaGetSymbolAddress((void**)&ht, g_ht);
    cudaGetSymbolAddress((void**)&qt8, g_qt8);
    cudaGetSymbolAddress((void**)&kt8, g_kt8);
    cudaGetSymbolAddress((void**)&v8,  g_v8);
    cudaGetSymbolAddress((void**)&ot, g_ot);
    cudaGetSymbolAddress((void**)&attn, g_attn);
    cudaGetSymbolAddress((void**)&attn8, g_attn8);
    cudaGetSymbolAddress((void**)&wq, g_wq);
    cudaGetSymbolAddress((void**)&wk, g_wk);
    cudaGetSymbolAddress((void**)&wv, g_wv);
    cudaGetSymbolAddress((void**)&wp, g_wp);

    cudaFuncSetAttribute(gemm_tc, cudaFuncAttributeMaxDynamicSharedMemorySize, SMEM_TOTAL);
    cudaFuncSetAttribute(gemm_f8, cudaFuncAttributeMaxDynamicSharedMemorySize, SMEM_TOTAL);

    cvt4_kernel<<<4*WN/256, 256>>>(q_w, k_w, v_w, p_w, wq, wk, wv, wp);
    gn_kernel<<<BATCH*GROUPS, 256>>>(x, gn_w, gn_b, ht);

    size_t sHT = (size_t)NPIX*CHN;
    size_t sCN = (size_t)CHN*NPIX;
    size_t sNN = (size_t)NPIX*NPIX;

    // q^T/k^T [i][c] e4m3 = ht @ W^T + b   (M=NPIX, N=CHN, K=CHN)
    dim3 qkgrid(CHN/BN, NPIX/BM, BATCH);
    gemm_tc<<<qkgrid, 128, SMEM_TOTAL>>>(ht, sHT, wq, 0, qt8, sHT, CHN,
                                         nullptr, q_b, nullptr, 1.f, CHN, 2);
    gemm_tc<<<qkgrid, 128, SMEM_TOTAL>>>(ht, sHT, wk, 0, kt8, sHT, CHN,
                                         nullptr, k_b, nullptr, 1.f, CHN, 2);
    // v [c][j] e4m3 = Wv @ ht + b          (M=CHN, N=NPIX, K=CHN)
    dim3 vgrid(NPIX/BN, CHN/BM, BATCH);
    gemm_tc<<<vgrid, 128, SMEM_TOTAL>>>(wv, 0, ht, sHT, v8, sCN, NPIX,
                                        v_b, nullptr, nullptr, 1.f, CHN, 2);
    // logits bf16 = scale * qt8 @ kt8^T    (M=N=NPIX, K=CHN), fp8 inputs
    dim3 lgrid(NPIX/BN, NPIX/BM, BATCH);
    gemm_f8<<<lgrid, 128, SMEM_TOTAL>>>(qt8, sHT, kt8, sHT, attn, sNN, NPIX,
                                        0.044194173824159216f, CHN);

    softmax_kernel<<<BATCH*NPIX, 256>>>(attn, attn8);

    // o^T bf16 = (attn8 @ v8^T) / 256      (M=NPIX, N=CHN, K=NPIX)
    dim3 ogrid(CHN/BN, NPIX/BM, BATCH);
    gemm_f8<<<ogrid, 128, SMEM_TOTAL>>>(attn8, sNN, v8, sCN, ot, sHT, CHN,
                                        1.0f/256.0f, NPIX);

    // out fp32 = Wp @ o^T + pb + x         (M=CHN, N=NPIX, K=CHN)
    dim3 pgrid(NPIX/BN, CHN/BM, BATCH);
    gemm_tc<<<pgrid, 128, SMEM_TOTAL>>>(wp, 0, ot, sHT, out, sCN, NPIX,
                                        p_b, nullptr, x, 1.f, CHN, 1);
}

// round 10
// speedup vs baseline: 1.2293x; 1.2293x over previous
#include <cuda_runtime.h>
#include <cuda_bf16.h>
#include <cstdint>
#include <math.h>

#define BATCH 8
#define CHN 512
#define NPIX 4096
#define GROUPS 32
#define CPG 16

// ---------------- scratch (__device__ globals) -------------------------------
__device__ __nv_bfloat16 g_ht[(size_t)BATCH*NPIX*CHN];     // h^T  [b][i][c]
__device__ __nv_bfloat16 g_qt[(size_t)BATCH*NPIX*CHN];     // q^T  [b][i][c]
__device__ __nv_bfloat16 g_kt[(size_t)BATCH*NPIX*CHN];     // k^T  [b][j][c]
__device__ __nv_bfloat16 g_v [(size_t)BATCH*CHN*NPIX];     // v    [b][c][j]
__device__ __nv_bfloat16 g_ot[(size_t)BATCH*NPIX*CHN];     // o^T  [b][i][c]
__device__ __nv_bfloat16 g_attn[(size_t)BATCH*NPIX*NPIX];  // exp(logits) [b][i][j]
__device__ float         g_rinv[(size_t)BATCH*NPIX];       // 1/rowsum
__device__ __nv_bfloat16 g_wq[CHN*CHN];
__device__ __nv_bfloat16 g_wk[CHN*CHN];
__device__ __nv_bfloat16 g_wv[CHN*CHN];
__device__ __nv_bfloat16 g_wp[CHN*CHN];

// ---------------- helpers ------------------------------------------------------
__device__ __forceinline__ uint32_t smem_u32(const void* p) {
    uint32_t a;
    asm("{ .reg .u64 t; cvta.to.shared.u64 t, %1; cvt.u32.u64 %0, t; }" : "=r"(a) : "l"(p));
    return a;
}
__device__ __forceinline__ void cpa16(uint32_t s, const void* g) {
    asm volatile("cp.async.cg.shared.global [%0], [%1], 16;" :: "r"(s), "l"(g) : "memory");
}
#define CPA_COMMIT() asm volatile("cp.async.commit_group;" ::: "memory")
#define CPA_WAIT1()  asm volatile("cp.async.wait_group 1;" ::: "memory")
#define CPA_WAIT0()  asm volatile("cp.async.wait_group 0;" ::: "memory")

__device__ __forceinline__ void ldsm4(uint32_t addr, uint32_t& r0, uint32_t& r1,
                                      uint32_t& r2, uint32_t& r3) {
    asm volatile("ldmatrix.sync.aligned.m8n8.x4.shared.b16 {%0,%1,%2,%3}, [%4];"
                 : "=r"(r0), "=r"(r1), "=r"(r2), "=r"(r3) : "r"(addr));
}

// ---------------- unified bf16 mma.sync GEMM ----------------------------------
// C[m][n] = f(scale * sum_k A[m][k]*B[n][k]); A,B k-contiguous
// mode 0: +bias_m +bias_n, bf16 out
// mode 1: +bias_m +resid, fp32 out
// mode 2: exp(acc*scale), bf16 out
// mode 3: acc*scale*rowscale[b*NPIX+m], bf16 out
#define BM 128
#define BN 128
#define BK 64
#define NSTAGE 3
#define ABYTES (BM*128)
#define BBYTES (BN*128)
#define STAGE_BYTES (ABYTES + BBYTES)
#define SMEM_TOTAL (NSTAGE*STAGE_BYTES)   // 96 KB

__global__ void __launch_bounds__(128, 2)
gemm_tc(const __nv_bfloat16* __restrict__ A, size_t strideA,
        const __nv_bfloat16* __restrict__ B, size_t strideB,
        const __nv_bfloat16* __restrict__ B2,
        void* __restrict__ Cv, void* __restrict__ Cv2,
        size_t strideC, int ldC,
        const float* __restrict__ bias_m,
        const float* __restrict__ bias_n,
        const float* __restrict__ bias_n2,
        const float* __restrict__ resid,
        const float* __restrict__ rowscale,
        float scale, int K, int mode) {
    extern __shared__ char smem[];
    uint32_t sb = smem_u32(smem);

    int tid  = threadIdx.x;
    int wid  = tid >> 5, lane = tid & 31;
    int wm = wid >> 1;
    int wn = wid & 1;
    int bz = blockIdx.z;
    if (B2 && bz >= (int)(gridDim.z >> 1)) {      // merged alt launch (q/k)
        bz -= gridDim.z >> 1;
        B = B2; bias_n = bias_n2; Cv = Cv2;
    }
    int m0 = blockIdx.y * BM;
    int n0 = blockIdx.x * BN;
    const __nv_bfloat16* Ab = A + (size_t)bz*strideA + (size_t)m0*K;
    const __nv_bfloat16* Bb = B + (size_t)bz*strideB + (size_t)n0*K;

    float acc[4][8][4];
    #pragma unroll
    for (int i = 0; i < 4; i++)
        #pragma unroll
        for (int j = 0; j < 8; j++)
            #pragma unroll
            for (int r = 0; r < 4; r++) acc[i][j][r] = 0.f;

    auto copy_stage = [&](int s, int k0) {
        uint32_t ab  = sb + s*STAGE_BYTES;
        uint32_t bbs = ab + ABYTES;
        #pragma unroll
        for (int i = 0; i < 8; i++) {
            int q = i*128 + tid;
            int r = q >> 3, c = q & 7;
            uint32_t off = r*128 + ((c ^ (r & 7)) << 4);
            cpa16(ab  + off, Ab + (size_t)r*K + k0 + c*8);
            cpa16(bbs + off, Bb + (size_t)r*K + k0 + c*8);
        }
        CPA_COMMIT();
    };

    int nt = K / BK;
    copy_stage(0, 0);
    copy_stage(1, BK);

    int arow = wm*64 + (lane & 15);
    int akc  = lane >> 4;
    int brow = wn*64 + (lane & 7) + ((lane >> 4) << 3);
    int bkc  = (lane >> 3) & 1;
    int xra = arow & 7, xrb = brow & 7;

    uint32_t a_base[4], b_base[4], xa[4], xb[4];
    #pragma unroll
    for (int i = 0; i < 4; i++) {
        a_base[i] = (uint32_t)(arow + i*16) * 128;
        b_base[i] = (uint32_t)(brow + i*16) * 128;
        xa[i] = (uint32_t)(((i*2 + akc) ^ xra) << 4);
        xb[i] = (uint32_t)(((i*2 + bkc) ^ xrb) << 4);
    }

    for (int it = 0; it < nt; it++) {
        if (it + 1 < nt) { CPA_WAIT1(); } else { CPA_WAIT0(); }
        __syncthreads();                         // single barrier per iteration
        if (it + 2 < nt) copy_stage((it + 2) % NSTAGE, (it + 2)*BK);

        uint32_t as = sb + (it % NSTAGE)*STAGE_BYTES;
        uint32_t bs = as + ABYTES;

        #pragma unroll
        for (int ks = 0; ks < 4; ks++) {
            uint32_t af[4][4], bf[8][2];
            #pragma unroll
            for (int am = 0; am < 4; am++)
                ldsm4(as + a_base[am] + xa[ks], af[am][0], af[am][1], af[am][2], af[am][3]);
            #pragma unroll
            for (int bt = 0; bt < 4; bt++)
                ldsm4(bs + b_base[bt] + xb[ks], bf[bt*2][0], bf[bt*2][1],
                                                bf[bt*2+1][0], bf[bt*2+1][1]);
            #pragma unroll
            for (int am = 0; am < 4; am++)
                #pragma unroll
                for (int an = 0; an < 8; an++) {
                    float* c = acc[am][an];
                    asm volatile(
                        "mma.sync.aligned.m16n8k16.row.col.f32.bf16.bf16.f32 "
                        "{%0,%1,%2,%3}, {%4,%5,%6,%7}, {%8,%9}, {%0,%1,%2,%3};"
                        : "+f"(c[0]), "+f"(c[1]), "+f"(c[2]), "+f"(c[3])
                        : "r"(af[am][0]), "r"(af[am][1]), "r"(af[am][2]), "r"(af[am][3]),
                          "r"(bf[an][0]), "r"(bf[an][1]));
                }
        }
    }

    // ---- epilogue ----
    int g = lane >> 2, t = lane & 3;
    #pragma unroll
    for (int am = 0; am < 4; am++) {
        int ml = m0 + wm*64 + am*16 + g;
        int mh = ml + 8;
        float pml = 0.f, pmh = 0.f;              // per-row add (bias) or mul (rowscale)
        if (mode == 3) {
            pml = rowscale[(size_t)bz*NPIX + ml];
            pmh = rowscale[(size_t)bz*NPIX + mh];
        } else if (bias_m) {
            pml = bias_m[ml]; pmh = bias_m[mh];
        }
        size_t rl = (size_t)bz*strideC + (size_t)ml*ldC;
        size_t rh = (size_t)bz*strideC + (size_t)mh*ldC;
        #pragma unroll
        for (int an = 0; an < 8; an++) {
            int ne = n0 + wn*64 + an*8 + 2*t;
            float v0 = acc[am][an][0], v1 = acc[am][an][1];
            float v2 = acc[am][an][2], v3 = acc[am][an][3];
            if (mode == 0) {
                v0 += pml; v1 += pml; v2 += pmh; v3 += pmh;
                if (bias_n) {
                    float b0 = __ldg(bias_n + ne), b1 = __ldg(bias_n + ne + 1);
                    v0 += b0; v1 += b1; v2 += b0; v3 += b1;
                }
                __nv_bfloat16* C = (__nv_bfloat16*)Cv;
                *reinterpret_cast<__nv_bfloat162*>(C + rl + ne) =
                    __nv_bfloat162{__float2bfloat16(v0), __float2bfloat16(v1)};
                *reinterpret_cast<__nv_bfloat162*>(C + rh + ne) =
                    __nv_bfloat162{__float2bfloat16(v2), __float2bfloat16(v3)};
            } else if (mode == 1) {
                float* C = (float*)Cv;
                float2 r0 = *reinterpret_cast<const float2*>(resid + rl + ne);
                float2 r1 = *reinterpret_cast<const float2*>(resid + rh + ne);
                *reinterpret_cast<float2*>(C + rl + ne) =
                    float2{v0 + pml + r0.x, v1 + pml + r0.y};
                *reinterpret_cast<float2*>(C + rh + ne) =
                    float2{v2 + pmh + r1.x, v3 + pmh + r1.y};
            } else if (mode == 2) {
                __nv_bfloat16* C = (__nv_bfloat16*)Cv;
                *reinterpret_cast<__nv_bfloat162*>(C + rl + ne) =
                    __nv_bfloat162{__float2bfloat16(__expf(v0*scale)),
                                   __float2bfloat16(__expf(v1*scale))};
                *reinterpret_cast<__nv_bfloat162*>(C + rh + ne) =
                    __nv_bfloat162{__float2bfloat16(__expf(v2*scale)),
                                   __float2bfloat16(__expf(v3*scale))};
            } else {
                __nv_bfloat16* C = (__nv_bfloat16*)Cv;
                *reinterpret_cast<__nv_bfloat162*>(C + rl + ne) =
                    __nv_bfloat162{__float2bfloat16(v0*pml), __float2bfloat16(v1*pml)};
                *reinterpret_cast<__nv_bfloat162*>(C + rh + ne) =
                    __nv_bfloat162{__float2bfloat16(v2*pmh), __float2bfloat16(v3*pmh)};
            }
        }
    }
}

// ---------------- fp32 -> bf16 weight convert (all 4 weights, 1 launch) -------
#define WN (CHN*CHN)
__global__ void cvt4_kernel(const float* __restrict__ s0, const float* __restrict__ s1,
                            const float* __restrict__ s2, const float* __restrict__ s3,
                            __nv_bfloat16* __restrict__ d0, __nv_bfloat16* __restrict__ d1,
                            __nv_bfloat16* __restrict__ d2, __nv_bfloat16* __restrict__ d3) {
    int i = blockIdx.x * blockDim.x + threadIdx.x;
    int sel = i >> 18;
    int off = i & (WN - 1);
    const float* s = sel == 0 ? s0 : sel == 1 ? s1 : sel == 2 ? s2 : s3;
    __nv_bfloat16* d = sel == 0 ? d0 : sel == 1 ? d1 : sel == 2 ? d2 : d3;
    d[off] = __float2bfloat16(s[off]);
}

// ---------------- GroupNorm -> h^T bf16 [b][i][c] -----------------------------
__global__ void gn_kernel(const float* __restrict__ x,
                          const float* __restrict__ w,
                          const float* __restrict__ b,
                          __nv_bfloat16* __restrict__ ht) {
    int batch = blockIdx.x >> 5;
    int grp   = blockIdx.x & 31;
    const float* xp = x + ((size_t)batch*CHN + (size_t)grp*CPG) * NPIX;
    const int GE = CPG * NPIX;
    int tid = threadIdx.x;

    float s = 0.f, ss = 0.f;
    for (int i = tid; i < GE; i += 256) {
        float v = xp[i];
        s += v; ss += v*v;
    }
    __shared__ float r1[256], r2[256];
    r1[tid] = s; r2[tid] = ss;
    __syncthreads();
    for (int st = 128; st > 0; st >>= 1) {
        if (tid < st) { r1[tid] += r1[tid+st]; r2[tid] += r2[tid+st]; }
        __syncthreads();
    }
    float mean = r1[0] / (float)GE;
    float var  = r2[0] / (float)GE - mean*mean;
    float rstd = rsqrtf(var + 1e-6f);

    float wl[CPG], bl[CPG];
    #pragma unroll
    for (int c = 0; c < CPG; c++) { wl[c] = w[grp*CPG+c]; bl[c] = b[grp*CPG+c]; }

    for (int n = tid; n < NPIX; n += 256) {
        union { __nv_bfloat16 v[CPG]; uint4 u[2]; } pk;
        #pragma unroll
        for (int c = 0; c < CPG; c++) {
            float xv = xp[(size_t)c*NPIX + n];
            pk.v[c] = __float2bfloat16((xv - mean) * rstd * wl[c] + bl[c]);
        }
        uint4* dst = reinterpret_cast<uint4*>(ht + ((size_t)batch*NPIX + n)*CHN + grp*CPG);
        dst[0] = pk.u[0]; dst[1] = pk.u[1];
    }
}

// ---------------- row sum of exp(logits) -> 1/sum ------------------------------
__global__ void rowsum_kernel(const __nv_bfloat16* __restrict__ attn,
                              float* __restrict__ rinv) {
    const __nv_bfloat16* p = attn + (size_t)blockIdx.x * NPIX;
    __shared__ float red[8];
    int tid = threadIdx.x, lane = tid & 31, wid = tid >> 5;

    float s = 0.f;
    for (int i = tid; i < NPIX/8; i += 256) {
        uint4 raw = reinterpret_cast<const uint4*>(p)[i];
        const __nv_bfloat162* h2 = reinterpret_cast<const __nv_bfloat162*>(&raw);
        #pragma unroll
        for (int j = 0; j < 4; j++) {
            float2 f = __bfloat1622float2(h2[j]);
            s += f.x + f.y;
        }
    }
    #pragma unroll
    for (int o = 16; o > 0; o >>= 1) s += __shfl_xor_sync(0xffffffffu, s, o);
    if (lane == 0) red[wid] = s;
    __syncthreads();
    if (tid == 0) {
        float m = 0.f;
        #pragma unroll
        for (int i = 0; i < 8; i++) m += red[i];
        rinv[blockIdx.x] = 1.0f / m;
    }
}

// ---------------- launch -------------------------------------------------------
extern "C" void kernel_launch(void* const* d_in, const int* in_sizes, int n_in,
                              void* d_out, int out_size) {
    const float* x    = (const float*)d_in[0];
    const float* gn_w = (const float*)d_in[1];
    const float* gn_b = (const float*)d_in[2];
    const float* q_w  = (const float*)d_in[3];
    const float* q_b  = (const float*)d_in[4];
    const float* k_w  = (const float*)d_in[5];
    const float* k_b  = (const float*)d_in[6];
    const float* v_w  = (const float*)d_in[7];
    const float* v_b  = (const float*)d_in[8];
    const float* p_w  = (const float*)d_in[9];
    const float* p_b  = (const float*)d_in[10];
    float* out = (float*)d_out;

    __nv_bfloat16 *ht, *qt, *kt, *v, *ot, *attn, *wq, *wk, *wv, *wp;
    float* rinv;
    cudaGetSymbolAddress((void**)&ht, g_ht);
    cudaGetSymbolAddress((void**)&qt, g_qt);
    cudaGetSymbolAddress((void**)&kt, g_kt);
    cudaGetSymbolAddress((void**)&v,  g_v);
    cudaGetSymbolAddress((void**)&ot, g_ot);
    cudaGetSymbolAddress((void**)&attn, g_attn);
    cudaGetSymbolAddress((void**)&rinv, g_rinv);
    cudaGetSymbolAddress((void**)&wq, g_wq);
    cudaGetSymbolAddress((void**)&wk, g_wk);
    cudaGetSymbolAddress((void**)&wv, g_wv);
    cudaGetSymbolAddress((void**)&wp, g_wp);

    cudaFuncSetAttribute(gemm_tc, cudaFuncAttributeMaxDynamicSharedMemorySize, SMEM_TOTAL);

    cvt4_kernel<<<4*WN/256, 256>>>(q_w, k_w, v_w, p_w, wq, wk, wv, wp);
    gn_kernel<<<BATCH*GROUPS, 256>>>(x, gn_w, gn_b, ht);

    size_t sHT = (size_t)NPIX*CHN;
    size_t sCN = (size_t)CHN*NPIX;
    size_t sNN = (size_t)NPIX*NPIX;

    // merged q/k: q^T,k^T [i][c] = ht @ W^T + b  (M=NPIX, N=CHN, K=CHN)
    dim3 qkgrid(CHN/BN, NPIX/BM, 2*BATCH);
    gemm_tc<<<qkgrid, 128, SMEM_TOTAL>>>(ht, sHT, wq, 0, wk, qt, kt, sHT, CHN,
                                         nullptr, q_b, k_b, nullptr, nullptr,
                                         1.f, CHN, 0);
    // v [c][j] = Wv @ ht + vb  (M=CHN, N=NPIX, K=CHN)
    dim3 vgrid(NPIX/BN, CHN/BM, BATCH);
    gemm_tc<<<vgrid, 128, SMEM_TOTAL>>>(wv, 0, ht, sHT, nullptr, v, nullptr, sCN, NPIX,
                                        v_b, nullptr, nullptr, nullptr, nullptr,
                                        1.f, CHN, 0);
    // attn = exp(scale * q·k)  (M=N=NPIX, K=CHN)
    dim3 lgrid(NPIX/BN, NPIX/BM, BATCH);
    gemm_tc<<<lgrid, 128, SMEM_TOTAL>>>(qt, sHT, kt, sHT, nullptr, attn, nullptr, sNN, NPIX,
                                        nullptr, nullptr, nullptr, nullptr, nullptr,
                                        0.044194173824159216f, CHN, 2);

    rowsum_kernel<<<BATCH*NPIX, 256>>>(attn, rinv);

    // o^T[i][c] = (attn @ v^T) * rinv[i]  (M=NPIX, N=CHN, K=NPIX)
    dim3 ogrid(CHN/BN, NPIX/BM, BATCH);
    gemm_tc<<<ogrid, 128, SMEM_TOTAL>>>(attn, sNN, v, sCN, nullptr, ot, nullptr, sHT, CHN,
                                        nullptr, nullptr, nullptr, nullptr, rinv,
                                        1.f, NPIX, 3);

    // out = Wp @ o^T + pb + x  (M=CHN, N=NPIX, K=CHN, fp32)
    dim3 pgrid(NPIX/BN, CHN/BM, BATCH);
    gemm_tc<<<pgrid, 128, SMEM_TOTAL>>>(wp, 0, ot, sHT, nullptr, out, nullptr, sCN, NPIX,
                                        p_b, nullptr, nullptr, x, nullptr,
                                        1.f, CHN, 1);
}

// round 12
// speedup vs baseline: 1.2605x; 1.0254x over previous
#include <cuda_runtime.h>
#include <cuda_bf16.h>
#include <cstdint>
#include <math.h>

#define BATCH 8
#define CHN 512
#define NPIX 4096
#define GROUPS 32
#define CPG 16

// ---------------- scratch (__device__ globals) -------------------------------
__device__ __nv_bfloat16 g_ht[(size_t)BATCH*NPIX*CHN];     // h^T  [b][i][c]
__device__ __nv_bfloat16 g_qt[(size_t)BATCH*NPIX*CHN];     // q^T  [b][i][c]
__device__ __nv_bfloat16 g_kt[(size_t)BATCH*NPIX*CHN];     // k^T  [b][j][c]
__device__ __nv_bfloat16 g_v [(size_t)BATCH*CHN*NPIX];     // v    [b][c][j]
__device__ __nv_bfloat16 g_ot[(size_t)BATCH*NPIX*CHN];     // o^T  [b][i][c]
__device__ __nv_bfloat16 g_attn[(size_t)BATCH*NPIX*NPIX];  // exp(logits) [b][i][j]
__device__ float         g_rsum[(size_t)BATCH*NPIX];       // row sums (atomic)
__device__ __nv_bfloat16 g_wq[CHN*CHN];
__device__ __nv_bfloat16 g_wk[CHN*CHN];
__device__ __nv_bfloat16 g_wv[CHN*CHN];
__device__ __nv_bfloat16 g_wp[CHN*CHN];

// ---------------- helpers ------------------------------------------------------
__device__ __forceinline__ uint32_t smem_u32(const void* p) {
    uint32_t a;
    asm("{ .reg .u64 t; cvta.to.shared.u64 t, %1; cvt.u32.u64 %0, t; }" : "=r"(a) : "l"(p));
    return a;
}
__device__ __forceinline__ void cpa16(uint32_t s, const void* g) {
    asm volatile("cp.async.cg.shared.global [%0], [%1], 16;" :: "r"(s), "l"(g) : "memory");
}
#define CPA_COMMIT() asm volatile("cp.async.commit_group;" ::: "memory")
#define CPA_WAIT1()  asm volatile("cp.async.wait_group 1;" ::: "memory")
#define CPA_WAIT0()  asm volatile("cp.async.wait_group 0;" ::: "memory")

__device__ __forceinline__ void ldsm4(uint32_t addr, uint32_t& r0, uint32_t& r1,
                                      uint32_t& r2, uint32_t& r3) {
    asm volatile("ldmatrix.sync.aligned.m8n8.x4.shared.b16 {%0,%1,%2,%3}, [%4];"
                 : "=r"(r0), "=r"(r1), "=r"(r2), "=r"(r3) : "r"(addr));
}

// ---------------- unified bf16 mma.sync GEMM (templated on BN) ----------------
// C[m][n] = f(sum_k A[m][k]*B[n][k]); A,B k-contiguous; BM=128 fixed.
// mode 0: +bias_m +bias_n, bf16 out
// mode 1: +bias_m +resid, fp32 out
// mode 2: exp(acc*scale), bf16 out, atomic row-sum into rsum
// mode 3: acc / rsum[b*NPIX+m], bf16 out
#define BM 128
#define BK 64
#define NSTAGE 3

template<int BN_T, int MINB>
__global__ void __launch_bounds__(128, MINB)
gemm_tc(const __nv_bfloat16* __restrict__ A, size_t strideA,
        const __nv_bfloat16* __restrict__ B, size_t strideB,
        const __nv_bfloat16* __restrict__ B2,
        void* __restrict__ Cv, void* __restrict__ Cv2,
        size_t strideC, int ldC,
        const float* __restrict__ bias_m,
        const float* __restrict__ bias_n,
        const float* __restrict__ bias_n2,
        const float* __restrict__ resid,
        float* __restrict__ rsum,
        float scale, int K, int mode) {
    constexpr int ABYTES = BM*128;
    constexpr int BBYTES = BN_T*128;
    constexpr int STAGE = ABYTES + BBYTES;
    constexpr int WNT = BN_T/2;        // warp N tile
    constexpr int ANC = WNT/8;         // mma n-count per warp
    constexpr int BTC = WNT/16;        // b-ldsm x4 tiles per warp (16 rows each)
    constexpr int BCP = BN_T/16;       // B copy iters

    extern __shared__ char smem[];
    uint32_t sb = smem_u32(smem);

    int tid  = threadIdx.x;
    int wid  = tid >> 5, lane = tid & 31;
    int wm = wid >> 1;
    int wn = wid & 1;
    int bz = blockIdx.z;
    if (B2 && bz >= (int)(gridDim.z >> 1)) {      // merged alt launch (q/k)
        bz -= gridDim.z >> 1;
        B = B2; bias_n = bias_n2; Cv = Cv2;
    }
    int m0 = blockIdx.y * BM;
    int n0 = blockIdx.x * BN_T;
    const __nv_bfloat16* Ab = A + (size_t)bz*strideA + (size_t)m0*K;
    const __nv_bfloat16* Bb = B + (size_t)bz*strideB + (size_t)n0*K;

    float acc[4][ANC][4];
    #pragma unroll
    for (int i = 0; i < 4; i++)
        #pragma unroll
        for (int j = 0; j < ANC; j++)
            #pragma unroll
            for (int r = 0; r < 4; r++) acc[i][j][r] = 0.f;

    auto copy_stage = [&](int s, int k0) {
        uint32_t ab  = sb + s*STAGE;
        uint32_t bbs = ab + ABYTES;
        #pragma unroll
        for (int i = 0; i < 8; i++) {
            int q = i*128 + tid;
            int r = q >> 3, c = q & 7;
            cpa16(ab + r*128 + ((c ^ (r & 7)) << 4), Ab + (size_t)r*K + k0 + c*8);
        }
        #pragma unroll
        for (int i = 0; i < BCP; i++) {
            int q = i*128 + tid;
            int r = q >> 3, c = q & 7;
            cpa16(bbs + r*128 + ((c ^ (r & 7)) << 4), Bb + (size_t)r*K + k0 + c*8);
        }
        CPA_COMMIT();
    };

    int nt = K / BK;
    copy_stage(0, 0);
    copy_stage(1, BK);

    int arow = wm*64 + (lane & 15);
    int akc  = lane >> 4;
    int brow = wn*WNT + (lane & 7) + ((lane >> 4) << 3);
    int bkc  = (lane >> 3) & 1;
    int xra = arow & 7, xrb = brow & 7;

    uint32_t a_base[4], b_base[BTC], xa[4], xb[4];
    #pragma unroll
    for (int i = 0; i < 4; i++) {
        a_base[i] = (uint32_t)(arow + i*16) * 128;
        xa[i] = (uint32_t)(((i*2 + akc) ^ xra) << 4);
        xb[i] = (uint32_t)(((i*2 + bkc) ^ xrb) << 4);
    }
    #pragma unroll
    for (int i = 0; i < BTC; i++)
        b_base[i] = (uint32_t)(brow + i*16) * 128;

    for (int it = 0; it < nt; it++) {
        if (it + 1 < nt) { CPA_WAIT1(); } else { CPA_WAIT0(); }
        __syncthreads();                         // single barrier per iteration
        if (it + 2 < nt) copy_stage((it + 2) % NSTAGE, (it + 2)*BK);

        uint32_t as = sb + (it % NSTAGE)*STAGE;
        uint32_t bs = as + ABYTES;

        #pragma unroll
        for (int ks = 0; ks < 4; ks++) {
            uint32_t af[4][4], bf[ANC][2];
            #pragma unroll
            for (int am = 0; am < 4; am++)
                ldsm4(as + a_base[am] + xa[ks], af[am][0], af[am][1], af[am][2], af[am][3]);
            #pragma unroll
            for (int bt = 0; bt < BTC; bt++)
                ldsm4(bs + b_base[bt] + xb[ks], bf[bt*2][0], bf[bt*2][1],
                                                bf[bt*2+1][0], bf[bt*2+1][1]);
            #pragma unroll
            for (int am = 0; am < 4; am++)
                #pragma unroll
                for (int an = 0; an < ANC; an++) {
                    float* c = acc[am][an];
                    asm volatile(
                        "mma.sync.aligned.m16n8k16.row.col.f32.bf16.bf16.f32 "
                        "{%0,%1,%2,%3}, {%4,%5,%6,%7}, {%8,%9}, {%0,%1,%2,%3};"
                        : "+f"(c[0]), "+f"(c[1]), "+f"(c[2]), "+f"(c[3])
                        : "r"(af[am][0]), "r"(af[am][1]), "r"(af[am][2]), "r"(af[am][3]),
                          "r"(bf[an][0]), "r"(bf[an][1]));
                }
        }
    }

    // ---- epilogue ----
    int g = lane >> 2, t = lane & 3;
    #pragma unroll
    for (int am = 0; am < 4; am++) {
        int ml = m0 + wm*64 + am*16 + g;
        int mh = ml + 8;
        float pml = 0.f, pmh = 0.f;
        if (mode == 3) {
            pml = 1.0f / rsum[(size_t)bz*NPIX + ml];
            pmh = 1.0f / rsum[(size_t)bz*NPIX + mh];
        } else if (bias_m) {
            pml = bias_m[ml]; pmh = bias_m[mh];
        }
        size_t rl = (size_t)bz*strideC + (size_t)ml*ldC;
        size_t rh = (size_t)bz*strideC + (size_t)mh*ldC;
        float s0 = 0.f, s1 = 0.f;
        #pragma unroll
        for (int an = 0; an < ANC; an++) {
            int ne = n0 + wn*WNT + an*8 + 2*t;
            float v0 = acc[am][an][0], v1 = acc[am][an][1];
            float v2 = acc[am][an][2], v3 = acc[am][an][3];
            if (mode == 0) {
                v0 += pml; v1 += pml; v2 += pmh; v3 += pmh;
                if (bias_n) {
                    float b0 = __ldg(bias_n + ne), b1 = __ldg(bias_n + ne + 1);
                    v0 += b0; v1 += b1; v2 += b0; v3 += b1;
                }
                __nv_bfloat16* C = (__nv_bfloat16*)Cv;
                *reinterpret_cast<__nv_bfloat162*>(C + rl + ne) =
                    __nv_bfloat162{__float2bfloat16(v0), __float2bfloat16(v1)};
                *reinterpret_cast<__nv_bfloat162*>(C + rh + ne) =
                    __nv_bfloat162{__float2bfloat16(v2), __float2bfloat16(v3)};
            } else if (mode == 1) {
                float* C = (float*)Cv;
                float2 r0 = *reinterpret_cast<const float2*>(resid + rl + ne);
                float2 r1 = *reinterpret_cast<const float2*>(resid + rh + ne);
                *reinterpret_cast<float2*>(C + rl + ne) =
                    float2{v0 + pml + r0.x, v1 + pml + r0.y};
                *reinterpret_cast<float2*>(C + rh + ne) =
                    float2{v2 + pmh + r1.x, v3 + pmh + r1.y};
            } else if (mode == 2) {
                float e0 = __expf(v0*scale), e1 = __expf(v1*scale);
                float e2 = __expf(v2*scale), e3 = __expf(v3*scale);
                s0 += e0 + e1; s1 += e2 + e3;
                __nv_bfloat16* C = (__nv_bfloat16*)Cv;
                *reinterpret_cast<__nv_bfloat162*>(C + rl + ne) =
                    __nv_bfloat162{__float2bfloat16(e0), __float2bfloat16(e1)};
                *reinterpret_cast<__nv_bfloat162*>(C + rh + ne) =
                    __nv_bfloat162{__float2bfloat16(e2), __float2bfloat16(e3)};
            } else {
                __nv_bfloat16* C = (__nv_bfloat16*)Cv;
                *reinterpret_cast<__nv_bfloat162*>(C + rl + ne) =
                    __nv_bfloat162{__float2bfloat16(v0*pml), __float2bfloat16(v1*pml)};
                *reinterpret_cast<__nv_bfloat162*>(C + rh + ne) =
                    __nv_bfloat162{__float2bfloat16(v2*pmh), __float2bfloat16(v3*pmh)};
            }
        }
        if (mode == 2) {   // reduce partial row sums over t-lanes, atomic once
            s0 += __shfl_xor_sync(0xffffffffu, s0, 1);
            s0 += __shfl_xor_sync(0xffffffffu, s0, 2);
            s1 += __shfl_xor_sync(0xffffffffu, s1, 1);
            s1 += __shfl_xor_sync(0xffffffffu, s1, 2);
            if (t == 0) {
                atomicAdd(&rsum[(size_t)bz*NPIX + ml], s0);
                atomicAdd(&rsum[(size_t)bz*NPIX + mh], s1);
            }
        }
    }
}

// ---------------- fp32 -> bf16 weight convert (all 4 weights, 1 launch) -------
#define WN (CHN*CHN)
__global__ void cvt4_kernel(const float* __restrict__ s0, const float* __restrict__ s1,
                            const float* __restrict__ s2, const float* __restrict__ s3,
                            __nv_bfloat16* __restrict__ d0, __nv_bfloat16* __restrict__ d1,
                            __nv_bfloat16* __restrict__ d2, __nv_bfloat16* __restrict__ d3) {
    int i = blockIdx.x * blockDim.x + threadIdx.x;
    int sel = i >> 18;
    int off = i & (WN - 1);
    const float* s = sel == 0 ? s0 : sel == 1 ? s1 : sel == 2 ? s2 : s3;
    __nv_bfloat16* d = sel == 0 ? d0 : sel == 1 ? d1 : sel == 2 ? d2 : d3;
    d[off] = __float2bfloat16(s[off]);
}

// ---------------- GroupNorm -> h^T bf16 [b][i][c] -----------------------------
__global__ void gn_kernel(const float* __restrict__ x,
                          const float* __restrict__ w,
                          const float* __restrict__ b,
                          __nv_bfloat16* __restrict__ ht) {
    int batch = blockIdx.x >> 5;
    int grp   = blockIdx.x & 31;
    const float* xp = x + ((size_t)batch*CHN + (size_t)grp*CPG) * NPIX;
    const int GE = CPG * NPIX;
    int tid = threadIdx.x;

    float s = 0.f, ss = 0.f;
    for (int i = tid; i < GE; i += 256) {
        float v = xp[i];
        s += v; ss += v*v;
    }
    __shared__ float r1[256], r2[256];
    r1[tid] = s; r2[tid] = ss;
    __syncthreads();
    for (int st = 128; st > 0; st >>= 1) {
        if (tid < st) { r1[tid] += r1[tid+st]; r2[tid] += r2[tid+st]; }
        __syncthreads();
    }
    float mean = r1[0] / (float)GE;
    float var  = r2[0] / (float)GE - mean*mean;
    float rstd = rsqrtf(var + 1e-6f);

    float wl[CPG], bl[CPG];
    #pragma unroll
    for (int c = 0; c < CPG; c++) { wl[c] = w[grp*CPG+c]; bl[c] = b[grp*CPG+c]; }

    for (int n = tid; n < NPIX; n += 256) {
        union { __nv_bfloat16 v[CPG]; uint4 u[2]; } pk;
        #pragma unroll
        for (int c = 0; c < CPG; c++) {
            float xv = xp[(size_t)c*NPIX + n];
            pk.v[c] = __float2bfloat16((xv - mean) * rstd * wl[c] + bl[c]);
        }
        uint4* dst = reinterpret_cast<uint4*>(ht + ((size_t)batch*NPIX + n)*CHN + grp*CPG);
        dst[0] = pk.u[0]; dst[1] = pk.u[1];
    }
}

// ---------------- launch -------------------------------------------------------
extern "C" void kernel_launch(void* const* d_in, const int* in_sizes, int n_in,
                              void* d_out, int out_size) {
    const float* x    = (const float*)d_in[0];
    const float* gn_w = (const float*)d_in[1];
    const float* gn_b = (const float*)d_in[2];
    const float* q_w  = (const float*)d_in[3];
    const float* q_b  = (const float*)d_in[4];
    const float* k_w  = (const float*)d_in[5];
    const float* k_b  = (const float*)d_in[6];
    const float* v_w  = (const float*)d_in[7];
    const float* v_b  = (const float*)d_in[8];
    const float* p_w  = (const float*)d_in[9];
    const float* p_b  = (const float*)d_in[10];
    float* out = (float*)d_out;

    __nv_bfloat16 *ht, *qt, *kt, *v, *ot, *attn, *wq, *wk, *wv, *wp;
    float* rsum;
    cudaGetSymbolAddress((void**)&ht, g_ht);
    cudaGetSymbolAddress((void**)&qt, g_qt);
    cudaGetSymbolAddress((void**)&kt, g_kt);
    cudaGetSymbolAddress((void**)&v,  g_v);
    cudaGetSymbolAddress((void**)&ot, g_ot);
    cudaGetSymbolAddress((void**)&attn, g_attn);
    cudaGetSymbolAddress((void**)&rsum, g_rsum);
    cudaGetSymbolAddress((void**)&wq, g_wq);
    cudaGetSymbolAddress((void**)&wk, g_wk);
    cudaGetSymbolAddress((void**)&wv, g_wv);
    cudaGetSymbolAddress((void**)&wp, g_wp);

    const int SM128 = NSTAGE*(BM*128 + 128*128);   // 96 KB
    const int SM64  = NSTAGE*(BM*128 +  64*128);   // 72 KB
    cudaFuncSetAttribute(gemm_tc<128,2>, cudaFuncAttributeMaxDynamicSharedMemorySize, SM128);
    cudaFuncSetAttribute(gemm_tc<64,3>,  cudaFuncAttributeMaxDynamicSharedMemorySize, SM64);

    cvt4_kernel<<<4*WN/256, 256>>>(q_w, k_w, v_w, p_w, wq, wk, wv, wp);
    gn_kernel<<<BATCH*GROUPS, 256>>>(x, gn_w, gn_b, ht);
    cudaMemsetAsync(rsum, 0, (size_t)BATCH*NPIX*sizeof(float));

    size_t sHT = (size_t)NPIX*CHN;
    size_t sCN = (size_t)CHN*NPIX;
    size_t sNN = (size_t)NPIX*NPIX;

    // merged q/k: q^T,k^T [i][c] = ht @ W^T + b  (M=NPIX, N=CHN, K=CHN)
    dim3 qkgrid(CHN/128, NPIX/BM, 2*BATCH);
    gemm_tc<128,2><<<qkgrid, 128, SM128>>>(ht, sHT, wq, 0, wk, qt, kt, sHT, CHN,
                                           nullptr, q_b, k_b, nullptr, nullptr,
                                           1.f, CHN, 0);
    // v [c][j] = Wv @ ht + vb  (M=CHN, N=NPIX, K=CHN)
    dim3 vgrid(NPIX/128, CHN/BM, BATCH);
    gemm_tc<128,2><<<vgrid, 128, SM128>>>(wv, 0, ht, sHT, nullptr, v, nullptr, sCN, NPIX,
                                          v_b, nullptr, nullptr, nullptr, nullptr,
                                          1.f, CHN, 0);
    // attn = exp(scale * q·k), atomic row sums  (M=N=NPIX, K=CHN)
    dim3 lgrid(NPIX/128, NPIX/BM, BATCH);
    gemm_tc<128,2><<<lgrid, 128, SM128>>>(qt, sHT, kt, sHT, nullptr, attn, nullptr, sNN, NPIX,
                                          nullptr, nullptr, nullptr, nullptr, rsum,
                                          0.044194173824159216f, CHN, 2);

    // o^T[i][c] = (attn @ v^T) / rsum[i]  (M=NPIX, N=CHN, K=NPIX), BN=64 for tail
    dim3 ogrid(CHN/64, NPIX/BM, BATCH);
    gemm_tc<64,3><<<ogrid, 128, SM64>>>(attn, sNN, v, sCN, nullptr, ot, nullptr, sHT, CHN,
                                        nullptr, nullptr, nullptr, nullptr, rsum,
                                        1.f, NPIX, 3);

    // out = Wp @ o^T + pb + x  (M=CHN, N=NPIX, K=CHN, fp32)
    dim3 pgrid(NPIX/128, CHN/BM, BATCH);
    gemm_tc<128,2><<<pgrid, 128, SM128>>>(wp, 0, ot, sHT, nullptr, out, nullptr, sCN, NPIX,
                                          p_b, nullptr, nullptr, x, nullptr,
                                          1.f, CHN, 1);
}

// round 13
// speedup vs baseline: 1.2802x; 1.0156x over previous
#include <cuda_runtime.h>
#include <cuda_bf16.h>
#include <cstdint>
#include <math.h>

#define BATCH 8
#define CHN 512
#define NPIX 4096
#define GROUPS 32
#define CPG 16

// ---------------- scratch (__device__ globals) -------------------------------
__device__ __nv_bfloat16 g_ht[(size_t)BATCH*NPIX*CHN];     // h^T  [b][i][c]
__device__ __nv_bfloat16 g_qt[(size_t)BATCH*NPIX*CHN];     // q^T  [b][i][c]
__device__ __nv_bfloat16 g_kt[(size_t)BATCH*NPIX*CHN];     // k^T  [b][j][c]
__device__ __nv_bfloat16 g_v [(size_t)BATCH*CHN*NPIX];     // v    [b][c][j]
__device__ __nv_bfloat16 g_ot[(size_t)BATCH*NPIX*CHN];     // o^T  [b][i][c]
__device__ __nv_bfloat16 g_attn[(size_t)BATCH*NPIX*NPIX];  // exp(logits) [b][i][j]
__device__ float         g_rsum[(size_t)BATCH*NPIX];       // row sums (atomic)
__device__ __nv_bfloat16 g_wq[CHN*CHN];
__device__ __nv_bfloat16 g_wk[CHN*CHN];
__device__ __nv_bfloat16 g_wv[CHN*CHN];
__device__ __nv_bfloat16 g_wp[CHN*CHN];

// ---------------- helpers ------------------------------------------------------
__device__ __forceinline__ uint32_t smem_u32(const void* p) {
    uint32_t a;
    asm("{ .reg .u64 t; cvta.to.shared.u64 t, %1; cvt.u32.u64 %0, t; }" : "=r"(a) : "l"(p));
    return a;
}
__device__ __forceinline__ void cpa16(uint32_t s, const void* g) {
    asm volatile("cp.async.cg.shared.global [%0], [%1], 16;" :: "r"(s), "l"(g) : "memory");
}
#define CPA_COMMIT() asm volatile("cp.async.commit_group;" ::: "memory")
#define CPA_WAIT1()  asm volatile("cp.async.wait_group 1;" ::: "memory")
#define CPA_WAIT0()  asm volatile("cp.async.wait_group 0;" ::: "memory")

__device__ __forceinline__ void ldsm4(uint32_t addr, uint32_t& r0, uint32_t& r1,
                                      uint32_t& r2, uint32_t& r3) {
    asm volatile("ldmatrix.sync.aligned.m8n8.x4.shared.b16 {%0,%1,%2,%3}, [%4];"
                 : "=r"(r0), "=r"(r1), "=r"(r2), "=r"(r3) : "r"(addr));
}

// ---------------- unified bf16 mma.sync GEMM (templated on BN) ----------------
// C[m][n] = f(sum_k A[m][k]*B[n][k]); A,B k-contiguous; BM=128 fixed.
// mode 0: +bias_m +bias_n, bf16 out
// mode 1: +bias_m +resid, fp32 out
// mode 2: exp2(acc*scale), bf16 out, atomic row-sum into rsum
// mode 3: acc / rsum[b*NPIX+m], bf16 out
#define BM 128
#define BK 64
#define NSTAGE 3

template<int BN_T, int MINB>
__global__ void __launch_bounds__(128, MINB)
gemm_tc(const __nv_bfloat16* __restrict__ A, size_t strideA,
        const __nv_bfloat16* __restrict__ B, size_t strideB,
        const __nv_bfloat16* __restrict__ B2,
        void* __restrict__ Cv, void* __restrict__ Cv2,
        size_t strideC, int ldC,
        const float* __restrict__ bias_m,
        const float* __restrict__ bias_n,
        const float* __restrict__ bias_n2,
        const float* __restrict__ resid,
        float* __restrict__ rsum,
        float scale, int K, int mode) {
    constexpr int ABYTES = BM*128;
    constexpr int BBYTES = BN_T*128;
    constexpr int STAGE = ABYTES + BBYTES;
    constexpr int WNT = BN_T/2;        // warp N tile
    constexpr int ANC = WNT/8;         // mma n-count per warp
    constexpr int BTC = WNT/16;        // b-ldsm x4 tiles per warp (16 rows each)
    constexpr int BCP = BN_T/16;       // B copy iters

    extern __shared__ char smem[];
    uint32_t sb = smem_u32(smem);

    int tid  = threadIdx.x;
    int wid  = tid >> 5, lane = tid & 31;
    int wm = wid >> 1;
    int wn = wid & 1;
    int bz = blockIdx.z;
    if (B2 && bz >= (int)(gridDim.z >> 1)) {      // merged alt launch (q/k)
        bz -= gridDim.z >> 1;
        B = B2; bias_n = bias_n2; Cv = Cv2;
    }
    int m0 = blockIdx.y * BM;
    int n0 = blockIdx.x * BN_T;
    const __nv_bfloat16* Ab = A + (size_t)bz*strideA + (size_t)m0*K;
    const __nv_bfloat16* Bb = B + (size_t)bz*strideB + (size_t)n0*K;

    float acc[4][ANC][4];
    #pragma unroll
    for (int i = 0; i < 4; i++)
        #pragma unroll
        for (int j = 0; j < ANC; j++)
            #pragma unroll
            for (int r = 0; r < 4; r++) acc[i][j][r] = 0.f;

    auto copy_stage = [&](int s, int k0) {
        uint32_t ab  = sb + s*STAGE;
        uint32_t bbs = ab + ABYTES;
        #pragma unroll
        for (int i = 0; i < 8; i++) {
            int q = i*128 + tid;
            int r = q >> 3, c = q & 7;
            cpa16(ab + r*128 + ((c ^ (r & 7)) << 4), Ab + (size_t)r*K + k0 + c*8);
        }
        #pragma unroll
        for (int i = 0; i < BCP; i++) {
            int q = i*128 + tid;
            int r = q >> 3, c = q & 7;
            cpa16(bbs + r*128 + ((c ^ (r & 7)) << 4), Bb + (size_t)r*K + k0 + c*8);
        }
        CPA_COMMIT();
    };

    int nt = K / BK;
    copy_stage(0, 0);
    copy_stage(1, BK);

    int arow = wm*64 + (lane & 15);
    int akc  = lane >> 4;
    int brow = wn*WNT + (lane & 7) + ((lane >> 4) << 3);
    int bkc  = (lane >> 3) & 1;
    int xra = arow & 7, xrb = brow & 7;

    uint32_t a_base[4], b_base[BTC], xa[4], xb[4];
    #pragma unroll
    for (int i = 0; i < 4; i++) {
        a_base[i] = (uint32_t)(arow + i*16) * 128;
        xa[i] = (uint32_t)(((i*2 + akc) ^ xra) << 4);
        xb[i] = (uint32_t)(((i*2 + bkc) ^ xrb) << 4);
    }
    #pragma unroll
    for (int i = 0; i < BTC; i++)
        b_base[i] = (uint32_t)(brow + i*16) * 128;

    for (int it = 0; it < nt; it++) {
        if (it + 1 < nt) { CPA_WAIT1(); } else { CPA_WAIT0(); }
        __syncthreads();                         // single barrier per iteration
        if (it + 2 < nt) copy_stage((it + 2) % NSTAGE, (it + 2)*BK);

        uint32_t as = sb + (it % NSTAGE)*STAGE;
        uint32_t bs = as + ABYTES;

        #pragma unroll
        for (int ks = 0; ks < 4; ks++) {
            uint32_t af[4][4], bf[ANC][2];
            #pragma unroll
            for (int am = 0; am < 4; am++)
                ldsm4(as + a_base[am] + xa[ks], af[am][0], af[am][1], af[am][2], af[am][3]);
            #pragma unroll
            for (int bt = 0; bt < BTC; bt++)
                ldsm4(bs + b_base[bt] + xb[ks], bf[bt*2][0], bf[bt*2][1],
                                                bf[bt*2+1][0], bf[bt*2+1][1]);
            #pragma unroll
            for (int am = 0; am < 4; am++)
                #pragma unroll
                for (int an = 0; an < ANC; an++) {
                    float* c = acc[am][an];
                    asm volatile(
                        "mma.sync.aligned.m16n8k16.row.col.f32.bf16.bf16.f32 "
                        "{%0,%1,%2,%3}, {%4,%5,%6,%7}, {%8,%9}, {%0,%1,%2,%3};"
                        : "+f"(c[0]), "+f"(c[1]), "+f"(c[2]), "+f"(c[3])
                        : "r"(af[am][0]), "r"(af[am][1]), "r"(af[am][2]), "r"(af[am][3]),
                          "r"(bf[an][0]), "r"(bf[an][1]));
                }
        }
    }

    // ---- epilogue ----
    int g = lane >> 2, t = lane & 3;
    #pragma unroll
    for (int am = 0; am < 4; am++) {
        int ml = m0 + wm*64 + am*16 + g;
        int mh = ml + 8;
        float pml = 0.f, pmh = 0.f;
        if (mode == 3) {
            pml = 1.0f / rsum[(size_t)bz*NPIX + ml];
            pmh = 1.0f / rsum[(size_t)bz*NPIX + mh];
        } else if (bias_m) {
            pml = bias_m[ml]; pmh = bias_m[mh];
        }
        size_t rl = (size_t)bz*strideC + (size_t)ml*ldC;
        size_t rh = (size_t)bz*strideC + (size_t)mh*ldC;
        float s0 = 0.f, s1 = 0.f;
        #pragma unroll
        for (int an = 0; an < ANC; an++) {
            int ne = n0 + wn*WNT + an*8 + 2*t;
            float v0 = acc[am][an][0], v1 = acc[am][an][1];
            float v2 = acc[am][an][2], v3 = acc[am][an][3];
            if (mode == 0) {
                v0 += pml; v1 += pml; v2 += pmh; v3 += pmh;
                if (bias_n) {
                    float b0 = __ldg(bias_n + ne), b1 = __ldg(bias_n + ne + 1);
                    v0 += b0; v1 += b1; v2 += b0; v3 += b1;
                }
                __nv_bfloat16* C = (__nv_bfloat16*)Cv;
                *reinterpret_cast<__nv_bfloat162*>(C + rl + ne) =
                    __nv_bfloat162{__float2bfloat16(v0), __float2bfloat16(v1)};
                *reinterpret_cast<__nv_bfloat162*>(C + rh + ne) =
                    __nv_bfloat162{__float2bfloat16(v2), __float2bfloat16(v3)};
            } else if (mode == 1) {
                float* C = (float*)Cv;
                float2 r0 = *reinterpret_cast<const float2*>(resid + rl + ne);
                float2 r1 = *reinterpret_cast<const float2*>(resid + rh + ne);
                *reinterpret_cast<float2*>(C + rl + ne) =
                    float2{v0 + pml + r0.x, v1 + pml + r0.y};
                *reinterpret_cast<float2*>(C + rh + ne) =
                    float2{v2 + pmh + r1.x, v3 + pmh + r1.y};
            } else if (mode == 2) {
                // scale already includes log2(e): exp(x*s) == exp2(x*scale)
                float e0 = exp2f(v0*scale), e1 = exp2f(v1*scale);
                float e2 = exp2f(v2*scale), e3 = exp2f(v3*scale);
                s0 += e0 + e1; s1 += e2 + e3;
                __nv_bfloat16* C = (__nv_bfloat16*)Cv;
                *reinterpret_cast<__nv_bfloat162*>(C + rl + ne) =
                    __nv_bfloat162{__float2bfloat16(e0), __float2bfloat16(e1)};
                *reinterpret_cast<__nv_bfloat162*>(C + rh + ne) =
                    __nv_bfloat162{__float2bfloat16(e2), __float2bfloat16(e3)};
            } else {
                __nv_bfloat16* C = (__nv_bfloat16*)Cv;
                *reinterpret_cast<__nv_bfloat162*>(C + rl + ne) =
                    __nv_bfloat162{__float2bfloat16(v0*pml), __float2bfloat16(v1*pml)};
                *reinterpret_cast<__nv_bfloat162*>(C + rh + ne) =
                    __nv_bfloat162{__float2bfloat16(v2*pmh), __float2bfloat16(v3*pmh)};
            }
        }
        if (mode == 2) {   // reduce partial row sums over t-lanes, atomic once
            s0 += __shfl_xor_sync(0xffffffffu, s0, 1);
            s0 += __shfl_xor_sync(0xffffffffu, s0, 2);
            s1 += __shfl_xor_sync(0xffffffffu, s1, 1);
            s1 += __shfl_xor_sync(0xffffffffu, s1, 2);
            if (t == 0) {
                atomicAdd(&rsum[(size_t)bz*NPIX + ml], s0);
                atomicAdd(&rsum[(size_t)bz*NPIX + mh], s1);
            }
        }
    }
}

// ---------------- fp32 -> bf16 weight convert (all 4 weights, 1 launch) -------
#define WN (CHN*CHN)
__global__ void cvt4_kernel(const float* __restrict__ s0, const float* __restrict__ s1,
                            const float* __restrict__ s2, const float* __restrict__ s3,
                            __nv_bfloat16* __restrict__ d0, __nv_bfloat16* __restrict__ d1,
                            __nv_bfloat16* __restrict__ d2, __nv_bfloat16* __restrict__ d3) {
    int i = blockIdx.x * blockDim.x + threadIdx.x;
    int sel = i >> 18;
    int off = i & (WN - 1);
    const float* s = sel == 0 ? s0 : sel == 1 ? s1 : sel == 2 ? s2 : s3;
    __nv_bfloat16* d = sel == 0 ? d0 : sel == 1 ? d1 : sel == 2 ? d2 : d3;
    d[off] = __float2bfloat16(s[off]);
}

// ---------------- GroupNorm -> h^T bf16 [b][i][c] -----------------------------
__global__ void gn_kernel(const float* __restrict__ x,
                          const float* __restrict__ w,
                          const float* __restrict__ b,
                          __nv_bfloat16* __restrict__ ht) {
    int batch = blockIdx.x >> 5;
    int grp   = blockIdx.x & 31;
    const float* xp = x + ((size_t)batch*CHN + (size_t)grp*CPG) * NPIX;
    const int GE = CPG * NPIX;
    int tid = threadIdx.x;

    float s = 0.f, ss = 0.f;
    for (int i = tid; i < GE; i += 256) {
        float v = xp[i];
        s += v; ss += v*v;
    }
    __shared__ float r1[256], r2[256];
    r1[tid] = s; r2[tid] = ss;
    __syncthreads();
    for (int st = 128; st > 0; st >>= 1) {
        if (tid < st) { r1[tid] += r1[tid+st]; r2[tid] += r2[tid+st]; }
        __syncthreads();
    }
    float mean = r1[0] / (float)GE;
    float var  = r2[0] / (float)GE - mean*mean;
    float rstd = rsqrtf(var + 1e-6f);

    float wl[CPG], bl[CPG];
    #pragma unroll
    for (int c = 0; c < CPG; c++) { wl[c] = w[grp*CPG+c]; bl[c] = b[grp*CPG+c]; }

    for (int n = tid; n < NPIX; n += 256) {
        union { __nv_bfloat16 v[CPG]; uint4 u[2]; } pk;
        #pragma unroll
        for (int c = 0; c < CPG; c++) {
            float xv = xp[(size_t)c*NPIX + n];
            pk.v[c] = __float2bfloat16((xv - mean) * rstd * wl[c] + bl[c]);
        }
        uint4* dst = reinterpret_cast<uint4*>(ht + ((size_t)batch*NPIX + n)*CHN + grp*CPG);
        dst[0] = pk.u[0]; dst[1] = pk.u[1];
    }
}

// ---------------- launch -------------------------------------------------------
extern "C" void kernel_launch(void* const* d_in, const int* in_sizes, int n_in,
                              void* d_out, int out_size) {
    const float* x    = (const float*)d_in[0];
    const float* gn_w = (const float*)d_in[1];
    const float* gn_b = (const float*)d_in[2];
    const float* q_w  = (const float*)d_in[3];
    const float* q_b  = (const float*)d_in[4];
    const float* k_w  = (const float*)d_in[5];
    const float* k_b  = (const float*)d_in[6];
    const float* v_w  = (const float*)d_in[7];
    const float* v_b  = (const float*)d_in[8];
    const float* p_w  = (const float*)d_in[9];
    const float* p_b  = (const float*)d_in[10];
    float* out = (float*)d_out;

    __nv_bfloat16 *ht, *qt, *kt, *v, *ot, *attn, *wq, *wk, *wv, *wp;
    float* rsum;
    cudaGetSymbolAddress((void**)&ht, g_ht);
    cudaGetSymbolAddress((void**)&qt, g_qt);
    cudaGetSymbolAddress((void**)&kt, g_kt);
    cudaGetSymbolAddress((void**)&v,  g_v);
    cudaGetSymbolAddress((void**)&ot, g_ot);
    cudaGetSymbolAddress((void**)&attn, g_attn);
    cudaGetSymbolAddress((void**)&rsum, g_rsum);
    cudaGetSymbolAddress((void**)&wq, g_wq);
    cudaGetSymbolAddress((void**)&wk, g_wk);
    cudaGetSymbolAddress((void**)&wv, g_wv);
    cudaGetSymbolAddress((void**)&wp, g_wp);

    const int SM128 = NSTAGE*(BM*128 + 128*128);   // 96 KB
    const int SM64  = NSTAGE*(BM*128 +  64*128);   // 72 KB
    cudaFuncSetAttribute(gemm_tc<128,2>, cudaFuncAttributeMaxDynamicSharedMemorySize, SM128);
    cudaFuncSetAttribute(gemm_tc<64,3>,  cudaFuncAttributeMaxDynamicSharedMemorySize, SM64);

    cvt4_kernel<<<4*WN/256, 256>>>(q_w, k_w, v_w, p_w, wq, wk, wv, wp);
    gn_kernel<<<BATCH*GROUPS, 256>>>(x, gn_w, gn_b, ht);
    cudaMemsetAsync(rsum, 0, (size_t)BATCH*NPIX*sizeof(float));

    size_t sHT = (size_t)NPIX*CHN;
    size_t sCN = (size_t)CHN*NPIX;
    size_t sNN = (size_t)NPIX*NPIX;

    // merged q/k: q^T,k^T [i][c] = ht @ W^T + b  (M=NPIX, N=CHN, K=CHN)
    dim3 qkgrid(CHN/128, NPIX/BM, 2*BATCH);
    gemm_tc<128,2><<<qkgrid, 128, SM128>>>(ht, sHT, wq, 0, wk, qt, kt, sHT, CHN,
                                           nullptr, q_b, k_b, nullptr, nullptr,
                                           1.f, CHN, 0);
    // v [c][j] = Wv @ ht + vb  (M=CHN, N=NPIX, K=CHN), BN=64 @3/SM for tail
    dim3 vgrid(NPIX/64, CHN/BM, BATCH);
    gemm_tc<64,3><<<vgrid, 128, SM64>>>(wv, 0, ht, sHT, nullptr, v, nullptr, sCN, NPIX,
                                        v_b, nullptr, nullptr, nullptr, nullptr,
                                        1.f, CHN, 0);
    // attn = exp2(scale' * q·k), atomic row sums  (M=N=NPIX, K=CHN)
    dim3 lgrid(NPIX/128, NPIX/BM, BATCH);
    gemm_tc<128,2><<<lgrid, 128, SM128>>>(qt, sHT, kt, sHT, nullptr, attn, nullptr, sNN, NPIX,
                                          nullptr, nullptr, nullptr, nullptr, rsum,
                                          0.044194173824159216f * 1.4426950408889634f,
                                          CHN, 2);

    // o^T[i][c] = (attn @ v^T) / rsum[i]  (M=NPIX, N=CHN, K=NPIX), BN=64 for tail
    dim3 ogrid(CHN/64, NPIX/BM, BATCH);
    gemm_tc<64,3><<<ogrid, 128, SM64>>>(attn, sNN, v, sCN, nullptr, ot, nullptr, sHT, CHN,
                                        nullptr, nullptr, nullptr, nullptr, rsum,
                                        1.f, NPIX, 3);

    // out = Wp @ o^T + pb + x  (M=CHN, N=NPIX, K=CHN, fp32), BN=64 for tail
    dim3 pgrid(NPIX/64, CHN/BM, BATCH);
    gemm_tc<64,3><<<pgrid, 128, SM64>>>(wp, 0, ot, sHT, nullptr, out, nullptr, sCN, NPIX,
                                        p_b, nullptr, nullptr, x, nullptr,
                                        1.f, CHN, 1);
}